// round 4
// baseline (speedup 1.0000x reference)
#include <cuda_runtime.h>
#include <cstdint>

// ====================================================================
// QuantumLayer: 3x (fft2,diag(q),ifft2) == ONE real 32-tap circulant
// along q; pz dead; out[q][d] = |noisy| at d or 63-d,
// flip = px ^ (fid < 0.9). JAX threefry (partitionable) on device.
// ====================================================================

static __device__ float        g_ck[32];    // composed circulant kernel
static __device__ float        g_esum[32];  // |sum_a ecc[a][q]|
static __device__ float        g_syn0[32];  // syn[0][q]
static __device__ unsigned int g_keys[4];   // k1 (amp), k2 (phase)

// ---------------- threefry2x32 ----------------
__device__ __forceinline__ unsigned int rotl32(unsigned int x, int r) {
    return __funnelshift_l(x, x, r);
}

__device__ __forceinline__ void tf2x32(unsigned int k0, unsigned int k1,
                                       unsigned int x0, unsigned int x1,
                                       unsigned int& o0, unsigned int& o1) {
    unsigned int k2 = k0 ^ k1 ^ 0x1BD11BDAu;
    x0 += k0; x1 += k1;
#define TFR4(a,b,c,d) \
    x0 += x1; x1 = rotl32(x1,(a)) ^ x0; \
    x0 += x1; x1 = rotl32(x1,(b)) ^ x0; \
    x0 += x1; x1 = rotl32(x1,(c)) ^ x0; \
    x0 += x1; x1 = rotl32(x1,(d)) ^ x0;
    TFR4(13,15,26, 6)  x0 += k1; x1 += k2 + 1u;
    TFR4(17,29,16,24)  x0 += k2; x1 += k0 + 2u;
    TFR4(13,15,26, 6)  x0 += k0; x1 += k1 + 3u;
    TFR4(17,29,16,24)  x0 += k1; x1 += k2 + 4u;
    TFR4(13,15,26, 6)  x0 += k2; x1 += k0 + 5u;
#undef TFR4
    o0 = x0; o1 = x1;
}

// partitionable random_bits: counter = (hi=0, lo=idx), fold the two outputs
__device__ __forceinline__ unsigned int tf_fold(unsigned int k0, unsigned int k1,
                                                unsigned int idx) {
    unsigned int o0, o1;
    tf2x32(k0, k1, 0u, idx, o0, o1);
    return o0 ^ o1;
}

// bits -> N(0,1), matching jax.random.normal float32 path
__device__ __forceinline__ float nrm_from_bits(unsigned int bits) {
    float f = __uint_as_float(0x3f800000u | (bits >> 9)) - 1.0f; // [0,1)
    const float LO = -0.99999994f;          // nextafter(-1,0) in f32
    float u = fmaxf(LO, fmaf(f, 2.0f, LO)); // (1 - LO) rounds to exactly 2.0f
    return 1.41421354f * erfinvf(u);
}

// ---------------- setup: QR -> thetas -> circulant, keys, scalars ----
// One 256-thread block; all O(256) vectors in SHARED (no local spill).
__global__ void qsetup(const float* __restrict__ rx, const float* __restrict__ ry,
                       const float* __restrict__ rz, const float* __restrict__ ecc,
                       const float* __restrict__ syn) {
    __shared__ double sA0[256], sA1[256], sV[256], sW[256], sT2[256];
    __shared__ double red[256];
    __shared__ double sTh[3][32];
    __shared__ double sCax[3][32], sT12[32];
    __shared__ double cw[32], sw[32];
    __shared__ double sc_tau, sc_sc, sc_tau2, sc_sc2, sc_tva, sc_tvu;

    const int tid = threadIdx.x;
    const float* ps[3] = { rx, ry, rz };

    // block tree-reduction into red[0]
    auto blkred = [&](double v) -> double {
        red[tid] = v; __syncthreads();
        for (int o = 128; o > 0; o >>= 1) {
            if (tid < o) red[tid] += red[tid + o];
            __syncthreads();
        }
        double r = red[0]; __syncthreads();
        return r;
    };

    for (int a = 0; a < 3; ++a) {
        const float* p = ps[a];
        sA0[tid] = (double)p[2*tid];
        sA1[tid] = (double)p[2*tid + 1];
        __syncthreads();

        double na = sqrt(blkred(sA0[tid] * sA0[tid]));
        if (tid == 0) {
            double alpha = sA0[0];
            double beta  = (alpha >= 0.0) ? -na : na;     // LAPACK slarfg sign
            sc_tau = (beta - alpha) / beta;
            sc_sc  = 1.0 / (alpha - beta);
        }
        __syncthreads();
        sV[tid] = (tid == 0) ? 1.0 : sA0[tid] * sc_sc;
        __syncthreads();

        double va = blkred(sV[tid] * sA1[tid]);
        if (tid == 0) sc_tva = sc_tau * va;
        __syncthreads();
        sW[tid] = sA1[tid] - sc_tva * sV[tid];
        __syncthreads();

        double nz = sqrt(blkred((tid >= 1) ? sW[tid] * sW[tid] : 0.0));
        if (tid == 0) {
            double alpha2 = sW[1];
            double beta2  = (alpha2 >= 0.0) ? -nz : nz;
            sc_tau2 = (beta2 - alpha2) / beta2;
            sc_sc2  = 1.0 / (alpha2 - beta2);
        }
        __syncthreads();
        {
            double u = (tid == 0) ? 0.0 : ((tid == 1) ? 1.0 : sW[tid] * sc_sc2);
            sT2[tid] = ((tid == 1) ? 1.0 : 0.0) - sc_tau2 * u;
        }
        __syncthreads();

        double vu = blkred(sV[tid] * sT2[tid]);
        if (tid == 0) sc_tvu = sc_tau * vu;
        __syncthreads();

        // theta[q] = mean of row q of Q.reshape(32,16) = sum of 16 entries /16
        if (tid < 32) {
            double t = 0.0;
            for (int i = 8*tid; i < 8*tid + 8; ++i) {
                double q0 = ((i == 0) ? 1.0 : 0.0) - sc_tau * sV[i];    // Q col 0
                double q1 = sT2[i] - sc_tvu * sV[i];                    // Q col 1
                t += q0 + q1;
            }
            sTh[a][tid] = t / 16.0;
        }
        __syncthreads();
    }

    // roots of unity tables
    const double PI = 3.14159265358979323846;
    if (tid < 32) {
        double wv = (2.0 * PI / 32.0) * (double)tid;
        cw[tid] = cos(wv);
        sw[tid] = sin(wv);
    }
    __syncthreads();

    // per-axis real circulant kernel c_a[j] = Re((1/32) sum_k d_k e^{+2pi i kj/32})
    if (tid < 32) {
        int j = tid;
        for (int a = 0; a < 3; ++a) {
            double acc = 0.0;
            for (int k = 0; k < 32; ++k) {
                double ang = 0.5 * sTh[a][2*(k >> 1)];   // theta[0::2] repeated
                double dre = cos(ang);
                double dim = (a < 2) ? 0.0 : ((k & 1) ? sin(ang) : -sin(ang));
                int w = (k * j) & 31;
                acc += dre * cw[w] - dim * sw[w];
            }
            sCax[a][j] = acc / 32.0;
        }
    }
    __syncthreads();

    // compose: ct = cx (*) cy (*) cz (circular convolution)
    if (tid < 32) {
        double s3 = 0.0;
        for (int m = 0; m < 32; ++m) s3 += sCax[0][m] * sCax[1][(tid - m) & 31];
        sT12[tid] = s3;
    }
    __syncthreads();
    if (tid < 32) {
        double s3 = 0.0;
        for (int m = 0; m < 32; ++m) s3 += sT12[m] * sCax[2][(tid - m) & 31];
        g_ck[tid] = (float)s3;
        g_esum[tid] = fabsf(ecc[tid] + ecc[32 + tid] + ecc[64 + tid]);
        g_syn0[tid] = syn[tid];
    }

    // jax.random.key(42) -> (0,42); split (partitionable):
    // k_i = full threefry output pair at counter (hi=0, lo=i)
    if (tid == 0) {
        unsigned int o0, o1;
        tf2x32(0u, 42u, 0u, 0u, o0, o1); g_keys[0] = o0; g_keys[1] = o1;
        tf2x32(0u, 42u, 0u, 1u, o0, o1); g_keys[2] = o0; g_keys[3] = o1;
    }
}

// ---------------- main: one warp per n-row (4096 rows) ----------------
#define NWARPS 8

__global__ __launch_bounds__(32 * NWARPS)
void qmain(const float* __restrict__ x, float* __restrict__ out) {
    __shared__ float s_ct[32], s_syn[32], s_es[32];
    __shared__ unsigned int s_keys[4];
    int tid = threadIdx.x;
    if (tid < 32) { s_ct[tid] = g_ck[tid]; s_syn[tid] = g_syn0[tid]; s_es[tid] = g_esum[tid]; }
    if (tid < 4)  s_keys[tid] = g_keys[tid];
    __syncthreads();

    const unsigned int K1a = s_keys[0], K1b = s_keys[1];
    const unsigned int K2a = s_keys[2], K2b = s_keys[3];

    int warp = tid >> 5, lane = tid & 31;
    int n = blockIdx.x * NWARPS + warp;          // 0..4095
    const float* xr   = x   + (size_t)n * 2048;
    float*       orow = out + (size_t)n * 2048;

    // row of x in registers: lane owns d=lane and d=lane+32
    float xa[32], xb[32];
    #pragma unroll
    for (int m = 0; m < 32; ++m) {
        xa[m] = xr[m * 64 + lane];
        xb[m] = xr[m * 64 + lane + 32];
    }

    unsigned int idx0 = (unsigned int)n * 2048u + (unsigned int)lane;

    #pragma unroll 1
    for (int q = 0; q < 32; ++q) {
        // circulant along q: state = sum_m ct[(q-m)&31] * x[m][d]
        float sA = 0.f, sB = 0.f;
        #pragma unroll
        for (int m = 0; m < 32; ++m) {
            float cc = s_ct[(q - m) & 31];
            sA = fmaf(cc, xa[m], sA);
            sB = fmaf(cc, xb[m], sB);
        }

        unsigned int ia = idx0 + (unsigned int)q * 64u;
        unsigned int ib = ia + 32u;
        float ampA = 0.01f  * nrm_from_bits(tf_fold(K1a, K1b, ia));
        float phA  = 0.005f * nrm_from_bits(tf_fold(K2a, K2b, ia));
        float ampB = 0.01f  * nrm_from_bits(tf_fold(K1a, K1b, ib));
        float phB  = 0.005f * nrm_from_bits(tf_fold(K2a, K2b, ib));

        float cA, snA, cB, snB;
        __sincosf(phA, &snA, &cA);
        __sincosf(phB, &snB, &cB);
        float gA = 1.f + ampA, gB = 1.f + ampB;
        float reA = gA * cA * sA, imA = gA * snA * sA;
        float reB = gB * cB * sB, imB = gB * snB * sB;

        float mA = sqrtf(reA*reA + imA*imA);
        float mB = sqrtf(reB*reB + imB*imB);

        // flipped S partners (d <-> 63-d): lane l slotA pairs lane 31-l slotB
        float sAf = __shfl_xor_sync(0xffffffffu, sB, 31);
        float sBf = __shfl_xor_sync(0xffffffffu, sA, 31);

        float ns  = mA*mA + mB*mB;          // sum |noisy|^2
        float sre = reA + reB;              // sum Re(noisy)
        float dNr = reA*sA  + reB*sB;       // conj(noisy) . S   (no flip)
        float dNi = imA*sA  + imB*sB;       //   (sign irrelevant under abs)
        float dFr = reA*sAf + reB*sBf;      // conj(noisy) . S_flipped
        float dFi = imA*sAf + imB*sBf;

        #pragma unroll
        for (int o = 16; o > 0; o >>= 1) {
            ns  += __shfl_xor_sync(0xffffffffu, ns,  o);
            sre += __shfl_xor_sync(0xffffffffu, sre, o);
            dNr += __shfl_xor_sync(0xffffffffu, dNr, o);
            dNi += __shfl_xor_sync(0xffffffffu, dNi, o);
            dFr += __shfl_xor_sync(0xffffffffu, dFr, o);
            dFi += __shfl_xor_sync(0xffffffffu, dFi, o);
        }

        float nn  = sqrtf(ns) + 1e-8f;
        bool  px  = (s_syn[q] * sre) > 0.f;
        float dr  = px ? dFr : dNr;
        float di  = px ? dFi : dNi;
        float fid = s_es[q] * sqrtf(dr*dr + di*di) / nn;
        bool  flip = px ^ (fid < 0.9f);

        float mAf = __shfl_xor_sync(0xffffffffu, mB, 31);
        float mBf = __shfl_xor_sync(0xffffffffu, mA, 31);
        float inv = 1.f / nn;
        orow[q * 64 + lane]      = (flip ? mAf : mA) * inv;
        orow[q * 64 + lane + 32] = (flip ? mBf : mB) * inv;
    }
}

extern "C" void kernel_launch(void* const* d_in, const int* in_sizes, int n_in,
                              void* d_out, int out_size) {
    const float* x   = (const float*)d_in[0];
    const float* rx  = (const float*)d_in[1];
    const float* ry  = (const float*)d_in[2];
    const float* rz  = (const float*)d_in[3];
    const float* ecc = (const float*)d_in[4];
    const float* syn = (const float*)d_in[5];
    float* out = (float*)d_out;

    qsetup<<<1, 256>>>(rx, ry, rz, ecc, syn);
    qmain<<<4096 / NWARPS, 32 * NWARPS>>>(x, out);
}

// round 5
// speedup vs baseline: 1.2424x; 1.2424x over previous
#include <cuda_runtime.h>
#include <cstdint>

// ====================================================================
// QuantumLayer: 3x (fft2,diag(q),ifft2) == ONE real 32-tap circulant
// along q; pz dead; out[q][d] = |noisy| at d or 63-d,
// flip = px ^ (fid < 0.9). JAX threefry (partitionable) on device.
// ====================================================================

static __device__ float        g_ck[32];    // composed circulant kernel
static __device__ float        g_esum[32];  // |sum_a ecc[a][q]|
static __device__ float        g_syn0[32];  // syn[0][q]
static __device__ unsigned int g_keys[4];   // k1 (amp), k2 (phase)

// ---------------- threefry2x32 ----------------
__device__ __forceinline__ unsigned int rotl32(unsigned int x, int r) {
    return __funnelshift_l(x, x, r);
}

__device__ __forceinline__ void tf2x32(unsigned int k0, unsigned int k1,
                                       unsigned int x0, unsigned int x1,
                                       unsigned int& o0, unsigned int& o1) {
    unsigned int k2 = k0 ^ k1 ^ 0x1BD11BDAu;
    x0 += k0; x1 += k1;
#define TFR4(a,b,c,d) \
    x0 += x1; x1 = rotl32(x1,(a)) ^ x0; \
    x0 += x1; x1 = rotl32(x1,(b)) ^ x0; \
    x0 += x1; x1 = rotl32(x1,(c)) ^ x0; \
    x0 += x1; x1 = rotl32(x1,(d)) ^ x0;
    TFR4(13,15,26, 6)  x0 += k1; x1 += k2 + 1u;
    TFR4(17,29,16,24)  x0 += k2; x1 += k0 + 2u;
    TFR4(13,15,26, 6)  x0 += k0; x1 += k1 + 3u;
    TFR4(17,29,16,24)  x0 += k1; x1 += k2 + 4u;
    TFR4(13,15,26, 6)  x0 += k2; x1 += k0 + 5u;
#undef TFR4
    o0 = x0; o1 = x1;
}

// partitionable random_bits: counter = (hi=0, lo=idx), fold the two outputs
__device__ __forceinline__ unsigned int tf_fold(unsigned int k0, unsigned int k1,
                                                unsigned int idx) {
    unsigned int o0, o1;
    tf2x32(k0, k1, 0u, idx, o0, o1);
    return o0 ^ o1;
}

// bits -> N(0,1), matching jax.random.normal float32 path
__device__ __forceinline__ float nrm_from_bits(unsigned int bits) {
    float f = __uint_as_float(0x3f800000u | (bits >> 9)) - 1.0f; // [0,1)
    const float LO = -0.99999994f;          // nextafter(-1,0) in f32
    float u = fmaxf(LO, fmaf(f, 2.0f, LO)); // (1 - LO) rounds to exactly 2.0f
    return 1.41421354f * erfinvf(u);
}

// ---------------- setup: QR -> thetas -> circulant, keys, scalars ----
// One 256-thread block; all O(256) vectors in SHARED (no local spill).
__global__ void qsetup(const float* __restrict__ rx, const float* __restrict__ ry,
                       const float* __restrict__ rz, const float* __restrict__ ecc,
                       const float* __restrict__ syn) {
    __shared__ double sA0[256], sA1[256], sV[256], sW[256], sT2[256];
    __shared__ double red[256];
    __shared__ double sTh[3][32];
    __shared__ double sCax[3][32], sT12[32];
    __shared__ double cw[32], sw[32];
    __shared__ double dreS[32], dimS[32];
    __shared__ double sc_tau, sc_sc, sc_tau2, sc_sc2, sc_tva, sc_tvu;

    const int tid = threadIdx.x;
    const float* ps[3] = { rx, ry, rz };

    // block tree-reduction into red[0]
    auto blkred = [&](double v) -> double {
        red[tid] = v; __syncthreads();
        for (int o = 128; o > 0; o >>= 1) {
            if (tid < o) red[tid] += red[tid + o];
            __syncthreads();
        }
        double r = red[0]; __syncthreads();
        return r;
    };

    for (int a = 0; a < 3; ++a) {
        const float* p = ps[a];
        sA0[tid] = (double)p[2*tid];
        sA1[tid] = (double)p[2*tid + 1];
        __syncthreads();

        double na = sqrt(blkred(sA0[tid] * sA0[tid]));
        if (tid == 0) {
            double alpha = sA0[0];
            double beta  = (alpha >= 0.0) ? -na : na;     // LAPACK slarfg sign
            sc_tau = (beta - alpha) / beta;
            sc_sc  = 1.0 / (alpha - beta);
        }
        __syncthreads();
        sV[tid] = (tid == 0) ? 1.0 : sA0[tid] * sc_sc;
        __syncthreads();

        double va = blkred(sV[tid] * sA1[tid]);
        if (tid == 0) sc_tva = sc_tau * va;
        __syncthreads();
        sW[tid] = sA1[tid] - sc_tva * sV[tid];
        __syncthreads();

        double nz = sqrt(blkred((tid >= 1) ? sW[tid] * sW[tid] : 0.0));
        if (tid == 0) {
            double alpha2 = sW[1];
            double beta2  = (alpha2 >= 0.0) ? -nz : nz;
            sc_tau2 = (beta2 - alpha2) / beta2;
            sc_sc2  = 1.0 / (alpha2 - beta2);
        }
        __syncthreads();
        {
            double u = (tid == 0) ? 0.0 : ((tid == 1) ? 1.0 : sW[tid] * sc_sc2);
            sT2[tid] = ((tid == 1) ? 1.0 : 0.0) - sc_tau2 * u;
        }
        __syncthreads();

        double vu = blkred(sV[tid] * sT2[tid]);
        if (tid == 0) sc_tvu = sc_tau * vu;
        __syncthreads();

        // theta[q] = mean of row q of Q.reshape(32,16) = sum of 16 entries /16
        if (tid < 32) {
            double t = 0.0;
            for (int i = 8*tid; i < 8*tid + 8; ++i) {
                double q0 = ((i == 0) ? 1.0 : 0.0) - sc_tau * sV[i];    // Q col 0
                double q1 = sT2[i] - sc_tvu * sV[i];                    // Q col 1
                t += q0 + q1;
            }
            sTh[a][tid] = t / 16.0;
        }
        __syncthreads();
    }

    // roots-of-unity tables
    const double PI = 3.14159265358979323846;
    if (tid < 32) {
        double wv = (2.0 * PI / 32.0) * (double)tid;
        cw[tid] = cos(wv);
        sw[tid] = sin(wv);
    }
    __syncthreads();

    // per-axis real circulant kernel c_a[j] = Re((1/32) sum_k d_k e^{+2pi i kj/32})
    // trig hoisted: dre/dim computed once per (axis,k)
    for (int a = 0; a < 3; ++a) {
        if (tid < 32) {
            double ang = 0.5 * sTh[a][2*(tid >> 1)];   // theta[0::2] repeated
            dreS[tid] = cos(ang);
            dimS[tid] = (a < 2) ? 0.0 : ((tid & 1) ? sin(ang) : -sin(ang));
        }
        __syncthreads();
        if (tid < 32) {
            int j = tid;
            double acc = 0.0;
            for (int k = 0; k < 32; ++k) {
                int w = (k * j) & 31;
                acc += dreS[k] * cw[w] - dimS[k] * sw[w];
            }
            sCax[a][j] = acc / 32.0;
        }
        __syncthreads();
    }

    // compose: ct = cx (*) cy (*) cz (circular convolution)
    if (tid < 32) {
        double s3 = 0.0;
        for (int m = 0; m < 32; ++m) s3 += sCax[0][m] * sCax[1][(tid - m) & 31];
        sT12[tid] = s3;
    }
    __syncthreads();
    if (tid < 32) {
        double s3 = 0.0;
        for (int m = 0; m < 32; ++m) s3 += sT12[m] * sCax[2][(tid - m) & 31];
        g_ck[tid] = (float)s3;
        g_esum[tid] = fabsf(ecc[tid] + ecc[32 + tid] + ecc[64 + tid]);
        g_syn0[tid] = syn[tid];
    }

    // jax.random.key(42) -> (0,42); split (partitionable):
    // k_i = full threefry output pair at counter (hi=0, lo=i)
    if (tid == 0) {
        unsigned int o0, o1;
        tf2x32(0u, 42u, 0u, 0u, o0, o1); g_keys[0] = o0; g_keys[1] = o1;
        tf2x32(0u, 42u, 0u, 1u, o0, o1); g_keys[2] = o0; g_keys[3] = o1;
    }
}

// ---------------- main: one warp per n-row (4096 rows) ----------------
#define NWARPS 8

__global__ __launch_bounds__(32 * NWARPS, 3)
void qmain(const float* __restrict__ x, float* __restrict__ out) {
    __shared__ float s_ct2[64];                 // unrolled circulant, immediate-offset taps
    __shared__ float s_syn[32], s_es[32];
    __shared__ unsigned int s_keys[4];
    __shared__ float xsh[NWARPS][32][32];       // [warp][m][lane]: second half of x row

    const int tid = threadIdx.x;
    if (tid < 63)                  s_ct2[tid] = g_ck[(tid + 1) & 31]; // s_ct2[q-m+31]=ct[(q-m)&31]
    if (tid >= 64  && tid < 96)    s_syn[tid - 64]  = g_syn0[tid - 64];
    if (tid >= 96  && tid < 128)   s_es[tid - 96]   = g_esum[tid - 96];
    if (tid >= 128 && tid < 132)   s_keys[tid - 128] = g_keys[tid - 128];
    __syncthreads();

    const unsigned int K1a = s_keys[0], K1b = s_keys[1];
    const unsigned int K2a = s_keys[2], K2b = s_keys[3];

    const int warp = tid >> 5, lane = tid & 31;
    const int n = blockIdx.x * NWARPS + warp;    // 0..4095
    const float* xr   = x   + (size_t)n * 2048;
    float*       orow = out + (size_t)n * 2048;

    // x row: lane owns d=lane (regs) and d=lane+32 (private smem column)
    float xa[32];
    #pragma unroll
    for (int m = 0; m < 32; ++m) {
        xa[m] = xr[m * 64 + lane];
        xsh[warp][m][lane] = xr[m * 64 + lane + 32];   // thread-private column: no sync needed
    }

    const unsigned int idx0 = (unsigned int)n * 2048u + (unsigned int)lane;

    #pragma unroll 1
    for (int q = 0; q < 32; ++q) {
        // circulant along q: state = sum_m ct[(q-m)&31] * x[m][d]
        const float* ctp = s_ct2 + q;
        float sA = 0.f, sB = 0.f;
        #pragma unroll
        for (int m = 0; m < 32; ++m) {
            float cc = ctp[31 - m];                  // immediate offsets, no index math
            sA = fmaf(cc, xa[m], sA);
            sB = fmaf(cc, xsh[warp][m][lane], sB);
        }

        unsigned int ia = idx0 + (unsigned int)q * 64u;
        unsigned int ib = ia + 32u;
        float ampA = 0.01f  * nrm_from_bits(tf_fold(K1a, K1b, ia));
        float phA  = 0.005f * nrm_from_bits(tf_fold(K2a, K2b, ia));
        float ampB = 0.01f  * nrm_from_bits(tf_fold(K1a, K1b, ib));
        float phB  = 0.005f * nrm_from_bits(tf_fold(K2a, K2b, ib));

        float gsA = fmaf(ampA, sA, sA);              // (1+amp)*S
        float gsB = fmaf(ampB, sB, sB);
        float cA, snA, cB, snB;
        __sincosf(phA, &snA, &cA);
        __sincosf(phB, &snB, &cB);
        float reA = gsA * cA, imA = gsA * snA;
        float reB = gsB * cB, imB = gsB * snB;

        // phase 1 reduction: norm^2 and Re-sum (|e^{i ph}|==1 => |noisy|=|gs|)
        float ns  = fmaf(gsA, gsA, gsB * gsB);
        float sre = reA + reB;
        #pragma unroll
        for (int o = 16; o > 0; o >>= 1) {
            ns  += __shfl_xor_sync(0xffffffffu, ns,  o);
            sre += __shfl_xor_sync(0xffffffffu, sre, o);
        }

        bool px = (s_syn[q] * sre) > 0.f;            // warp-uniform

        // phase 2: only the selected dot (flip if px)
        float drp, dip;
        if (px) {
            float sAf = __shfl_xor_sync(0xffffffffu, sB, 31);  // S at 63-d
            float sBf = __shfl_xor_sync(0xffffffffu, sA, 31);
            drp = fmaf(reA, sAf, reB * sBf);
            dip = fmaf(imA, sAf, imB * sBf);
        } else {
            drp = fmaf(reA, sA, reB * sB);
            dip = fmaf(imA, sA, imB * sB);
        }
        #pragma unroll
        for (int o = 16; o > 0; o >>= 1) {
            drp += __shfl_xor_sync(0xffffffffu, drp, o);
            dip += __shfl_xor_sync(0xffffffffu, dip, o);
        }

        float nn  = sqrtf(ns) + 1e-8f;
        float inv = __fdividef(1.f, nn);
        float fid = s_es[q] * sqrtf(fmaf(drp, drp, dip * dip)) * inv;
        bool  flip = px != (fid < 0.9f);             // warp-uniform

        float mA = fabsf(gsA), mB = fabsf(gsB);
        float oA, oB;
        if (flip) {
            oA = __shfl_xor_sync(0xffffffffu, mB, 31);
            oB = __shfl_xor_sync(0xffffffffu, mA, 31);
        } else {
            oA = mA; oB = mB;
        }
        orow[q * 64 + lane]      = oA * inv;
        orow[q * 64 + lane + 32] = oB * inv;
    }
}

extern "C" void kernel_launch(void* const* d_in, const int* in_sizes, int n_in,
                              void* d_out, int out_size) {
    const float* x   = (const float*)d_in[0];
    const float* rx  = (const float*)d_in[1];
    const float* ry  = (const float*)d_in[2];
    const float* rz  = (const float*)d_in[3];
    const float* ecc = (const float*)d_in[4];
    const float* syn = (const float*)d_in[5];
    float* out = (float*)d_out;

    qsetup<<<1, 256>>>(rx, ry, rz, ecc, syn);
    qmain<<<4096 / NWARPS, 32 * NWARPS>>>(x, out);
}

// round 6
// speedup vs baseline: 1.4449x; 1.1630x over previous
#include <cuda_runtime.h>
#include <cstdint>

// ====================================================================
// QuantumLayer: 3x (fft2,diag(q),ifft2) == ONE real 32-tap circulant
// along q; pz dead; out[q][d] = |noisy| at d or 63-d,
// flip = px ^ (fid < 0.9). JAX threefry (partitionable) on device.
// ====================================================================

static __device__ float        g_ck[32];    // composed circulant kernel
static __device__ float        g_esum[32];  // |sum_a ecc[a][q]|
static __device__ float        g_syn0[32];  // syn[0][q]
static __device__ unsigned int g_keys[4];   // k1 (amp), k2 (phase)
static __device__ unsigned int g_row;       // row ticket counter

// ---------------- threefry2x32 ----------------
__device__ __forceinline__ unsigned int rotl32(unsigned int x, int r) {
    return __funnelshift_l(x, x, r);
}

__device__ __forceinline__ void tf2x32(unsigned int k0, unsigned int k1,
                                       unsigned int x0, unsigned int x1,
                                       unsigned int& o0, unsigned int& o1) {
    unsigned int k2 = k0 ^ k1 ^ 0x1BD11BDAu;
    x0 += k0; x1 += k1;
#define TFR4(a,b,c,d) \
    x0 += x1; x1 = rotl32(x1,(a)) ^ x0; \
    x0 += x1; x1 = rotl32(x1,(b)) ^ x0; \
    x0 += x1; x1 = rotl32(x1,(c)) ^ x0; \
    x0 += x1; x1 = rotl32(x1,(d)) ^ x0;
    TFR4(13,15,26, 6)  x0 += k1; x1 += k2 + 1u;
    TFR4(17,29,16,24)  x0 += k2; x1 += k0 + 2u;
    TFR4(13,15,26, 6)  x0 += k0; x1 += k1 + 3u;
    TFR4(17,29,16,24)  x0 += k1; x1 += k2 + 4u;
    TFR4(13,15,26, 6)  x0 += k2; x1 += k0 + 5u;
#undef TFR4
    o0 = x0; o1 = x1;
}

// partitionable random_bits: counter = (hi=0, lo=idx), fold the two outputs
__device__ __forceinline__ unsigned int tf_fold(unsigned int k0, unsigned int k1,
                                                unsigned int idx) {
    unsigned int o0, o1;
    tf2x32(k0, k1, 0u, idx, o0, o1);
    return o0 ^ o1;
}

// bits -> N(0,1), matching jax.random.normal float32 path
__device__ __forceinline__ float nrm_from_bits(unsigned int bits) {
    float f = __uint_as_float(0x3f800000u | (bits >> 9)) - 1.0f; // [0,1)
    const float LO = -0.99999994f;          // nextafter(-1,0) in f32
    float u = fmaxf(LO, fmaf(f, 2.0f, LO)); // (1 - LO) rounds to exactly 2.0f
    return 1.41421354f * erfinvf(u);
}

// ---------------- setup: QR -> thetas -> circulant, keys, scalars ----
__global__ void qsetup(const float* __restrict__ rx, const float* __restrict__ ry,
                       const float* __restrict__ rz, const float* __restrict__ ecc,
                       const float* __restrict__ syn) {
    __shared__ double sA0[256], sA1[256], sV[256], sW[256], sT2[256];
    __shared__ double red[256];
    __shared__ double sTh[3][32];
    __shared__ double sCax[3][32], sT12[32];
    __shared__ double cw[32], sw[32];
    __shared__ double dreS[32], dimS[32];
    __shared__ double sc_tau, sc_sc, sc_tau2, sc_sc2, sc_tva, sc_tvu;

    const int tid = threadIdx.x;
    const float* ps[3] = { rx, ry, rz };

    auto blkred = [&](double v) -> double {
        red[tid] = v; __syncthreads();
        for (int o = 128; o > 0; o >>= 1) {
            if (tid < o) red[tid] += red[tid + o];
            __syncthreads();
        }
        double r = red[0]; __syncthreads();
        return r;
    };

    for (int a = 0; a < 3; ++a) {
        const float* p = ps[a];
        sA0[tid] = (double)p[2*tid];
        sA1[tid] = (double)p[2*tid + 1];
        __syncthreads();

        double na = sqrt(blkred(sA0[tid] * sA0[tid]));
        if (tid == 0) {
            double alpha = sA0[0];
            double beta  = (alpha >= 0.0) ? -na : na;     // LAPACK slarfg sign
            sc_tau = (beta - alpha) / beta;
            sc_sc  = 1.0 / (alpha - beta);
        }
        __syncthreads();
        sV[tid] = (tid == 0) ? 1.0 : sA0[tid] * sc_sc;
        __syncthreads();

        double va = blkred(sV[tid] * sA1[tid]);
        if (tid == 0) sc_tva = sc_tau * va;
        __syncthreads();
        sW[tid] = sA1[tid] - sc_tva * sV[tid];
        __syncthreads();

        double nz = sqrt(blkred((tid >= 1) ? sW[tid] * sW[tid] : 0.0));
        if (tid == 0) {
            double alpha2 = sW[1];
            double beta2  = (alpha2 >= 0.0) ? -nz : nz;
            sc_tau2 = (beta2 - alpha2) / beta2;
            sc_sc2  = 1.0 / (alpha2 - beta2);
        }
        __syncthreads();
        {
            double u = (tid == 0) ? 0.0 : ((tid == 1) ? 1.0 : sW[tid] * sc_sc2);
            sT2[tid] = ((tid == 1) ? 1.0 : 0.0) - sc_tau2 * u;
        }
        __syncthreads();

        double vu = blkred(sV[tid] * sT2[tid]);
        if (tid == 0) sc_tvu = sc_tau * vu;
        __syncthreads();

        if (tid < 32) {
            double t = 0.0;
            for (int i = 8*tid; i < 8*tid + 8; ++i) {
                double q0 = ((i == 0) ? 1.0 : 0.0) - sc_tau * sV[i];    // Q col 0
                double q1 = sT2[i] - sc_tvu * sV[i];                    // Q col 1
                t += q0 + q1;
            }
            sTh[a][tid] = t / 16.0;
        }
        __syncthreads();
    }

    const double PI = 3.14159265358979323846;
    if (tid < 32) {
        double wv = (2.0 * PI / 32.0) * (double)tid;
        cw[tid] = cos(wv);
        sw[tid] = sin(wv);
    }
    __syncthreads();

    for (int a = 0; a < 3; ++a) {
        if (tid < 32) {
            double ang = 0.5 * sTh[a][2*(tid >> 1)];   // theta[0::2] repeated
            dreS[tid] = cos(ang);
            dimS[tid] = (a < 2) ? 0.0 : ((tid & 1) ? sin(ang) : -sin(ang));
        }
        __syncthreads();
        if (tid < 32) {
            int j = tid;
            double acc = 0.0;
            for (int k = 0; k < 32; ++k) {
                int w = (k * j) & 31;
                acc += dreS[k] * cw[w] - dimS[k] * sw[w];
            }
            sCax[a][j] = acc / 32.0;
        }
        __syncthreads();
    }

    if (tid < 32) {
        double s3 = 0.0;
        for (int m = 0; m < 32; ++m) s3 += sCax[0][m] * sCax[1][(tid - m) & 31];
        sT12[tid] = s3;
    }
    __syncthreads();
    if (tid < 32) {
        double s3 = 0.0;
        for (int m = 0; m < 32; ++m) s3 += sT12[m] * sCax[2][(tid - m) & 31];
        g_ck[tid] = (float)s3;
        g_esum[tid] = fabsf(ecc[tid] + ecc[32 + tid] + ecc[64 + tid]);
        g_syn0[tid] = syn[tid];
    }

    if (tid == 0) {
        unsigned int o0, o1;
        tf2x32(0u, 42u, 0u, 0u, o0, o1); g_keys[0] = o0; g_keys[1] = o1;
        tf2x32(0u, 42u, 0u, 1u, o0, o1); g_keys[2] = o0; g_keys[3] = o1;
        g_row = 0u;                      // reset row tickets every launch
    }
}

// ---------------- main: warps pull rows from a ticket counter --------
#define QW 4                       // warps per block
#define NROWS 4096u

__global__ __launch_bounds__(32 * QW, 6)
void qmain(const float* __restrict__ x, float* __restrict__ out) {
    __shared__ float  s_ct2[64];                // s_ct2[j] = ct[(j+1)&31]
    __shared__ float  s_syn[32], s_es[32];
    __shared__ unsigned int s_keys[4];
    __shared__ float2 xsh[QW][32][32];          // [warp][m][lane] = (x[2l], x[2l+1])

    const int tid = threadIdx.x;
    if (tid < 64)                s_ct2[tid]      = g_ck[(tid + 1) & 31];
    if (tid >= 64 && tid < 96)   s_syn[tid - 64] = g_syn0[tid - 64];
    if (tid >= 96 && tid < 128)  s_es[tid - 96]  = g_esum[tid - 96];
    if (tid < 4)                 s_keys[tid]     = g_keys[tid];
    __syncthreads();

    const unsigned int K1a = s_keys[0], K1b = s_keys[1];
    const unsigned int K2a = s_keys[2], K2b = s_keys[3];

    const int warp = tid >> 5, lane = tid & 31;

    for (;;) {
        unsigned int row;
        if (lane == 0) row = atomicAdd(&g_row, 1u);
        row = __shfl_sync(0xffffffffu, row, 0);
        if (row >= NROWS) break;

        const float2* xr2   = (const float2*)(x   + (size_t)row * 2048);
        float2*       orow2 = (float2*)      (out + (size_t)row * 2048);

        // lane owns d=2*lane (.x) and d=2*lane+1 (.y)
        #pragma unroll
        for (int m = 0; m < 32; ++m)
            xsh[warp][m][lane] = xr2[m * 32 + lane];
        __syncwarp();

        const unsigned int idx0 = row * 2048u + 2u * (unsigned int)lane;

        #pragma unroll 1
        for (int q = 0; q < 32; q += 2) {
            // circulant along q for q and q+1 (shared x reads)
            const float* cp = s_ct2 + q + 31;    // cp[-m] = ct[(q-m)&31]
            float sA0 = 0.f, sB0 = 0.f, sA1 = 0.f, sB1 = 0.f;
            #pragma unroll
            for (int m = 0; m < 32; ++m) {
                float2 xm = xsh[warp][m][lane];
                float c0 = cp[-m];
                float c1 = cp[1 - m];
                sA0 = fmaf(c0, xm.x, sA0); sB0 = fmaf(c0, xm.y, sB0);
                sA1 = fmaf(c1, xm.x, sA1); sB1 = fmaf(c1, xm.y, sB1);
            }

            // 8 independent threefry chains (ILP)
            const unsigned int i0 = idx0 + (unsigned int)q * 64u;
            unsigned int bA0a = tf_fold(K1a, K1b, i0);
            unsigned int bA0p = tf_fold(K2a, K2b, i0);
            unsigned int bB0a = tf_fold(K1a, K1b, i0 + 1u);
            unsigned int bB0p = tf_fold(K2a, K2b, i0 + 1u);
            unsigned int bA1a = tf_fold(K1a, K1b, i0 + 64u);
            unsigned int bA1p = tf_fold(K2a, K2b, i0 + 64u);
            unsigned int bB1a = tf_fold(K1a, K1b, i0 + 65u);
            unsigned int bB1p = tf_fold(K2a, K2b, i0 + 65u);

            float ampA0 = 0.01f  * nrm_from_bits(bA0a);
            float phA0  = 0.005f * nrm_from_bits(bA0p);
            float ampB0 = 0.01f  * nrm_from_bits(bB0a);
            float phB0  = 0.005f * nrm_from_bits(bB0p);
            float ampA1 = 0.01f  * nrm_from_bits(bA1a);
            float phA1  = 0.005f * nrm_from_bits(bA1p);
            float ampB1 = 0.01f  * nrm_from_bits(bB1a);
            float phB1  = 0.005f * nrm_from_bits(bB1p);

            float gsA0 = fmaf(ampA0, sA0, sA0), gsB0 = fmaf(ampB0, sB0, sB0);
            float gsA1 = fmaf(ampA1, sA1, sA1), gsB1 = fmaf(ampB1, sB1, sB1);

            float cA0, snA0, cB0, snB0, cA1, snA1, cB1, snB1;
            __sincosf(phA0, &snA0, &cA0);
            __sincosf(phB0, &snB0, &cB0);
            __sincosf(phA1, &snA1, &cA1);
            __sincosf(phB1, &snB1, &cB1);
            float reA0 = gsA0 * cA0, imA0 = gsA0 * snA0;
            float reB0 = gsB0 * cB0, imB0 = gsB0 * snB0;
            float reA1 = gsA1 * cA1, imA1 = gsA1 * snA1;
            float reB1 = gsB1 * cB1, imB1 = gsB1 * snB1;

            // phase 1: norm^2 and Re-sum for both q (|e^{i ph}|==1)
            float ns0  = fmaf(gsA0, gsA0, gsB0 * gsB0);
            float ns1  = fmaf(gsA1, gsA1, gsB1 * gsB1);
            float sre0 = reA0 + reB0;
            float sre1 = reA1 + reB1;
            #pragma unroll
            for (int o = 16; o > 0; o >>= 1) {
                ns0  += __shfl_xor_sync(0xffffffffu, ns0,  o);
                ns1  += __shfl_xor_sync(0xffffffffu, ns1,  o);
                sre0 += __shfl_xor_sync(0xffffffffu, sre0, o);
                sre1 += __shfl_xor_sync(0xffffffffu, sre1, o);
            }
            bool px0 = (s_syn[q]     * sre0) > 0.f;   // warp-uniform
            bool px1 = (s_syn[q + 1] * sre1) > 0.f;

            // phase 2: selected dot only (flip if px)
            float dr0, di0, dr1, di1;
            if (px0) {
                float sAf = __shfl_xor_sync(0xffffffffu, sB0, 31);
                float sBf = __shfl_xor_sync(0xffffffffu, sA0, 31);
                dr0 = fmaf(reA0, sAf, reB0 * sBf);
                di0 = fmaf(imA0, sAf, imB0 * sBf);
            } else {
                dr0 = fmaf(reA0, sA0, reB0 * sB0);
                di0 = fmaf(imA0, sA0, imB0 * sB0);
            }
            if (px1) {
                float sAf = __shfl_xor_sync(0xffffffffu, sB1, 31);
                float sBf = __shfl_xor_sync(0xffffffffu, sA1, 31);
                dr1 = fmaf(reA1, sAf, reB1 * sBf);
                di1 = fmaf(imA1, sAf, imB1 * sBf);
            } else {
                dr1 = fmaf(reA1, sA1, reB1 * sB1);
                di1 = fmaf(imA1, sA1, imB1 * sB1);
            }
            #pragma unroll
            for (int o = 16; o > 0; o >>= 1) {
                dr0 += __shfl_xor_sync(0xffffffffu, dr0, o);
                di0 += __shfl_xor_sync(0xffffffffu, di0, o);
                dr1 += __shfl_xor_sync(0xffffffffu, dr1, o);
                di1 += __shfl_xor_sync(0xffffffffu, di1, o);
            }

            float nn0  = sqrtf(ns0) + 1e-8f;
            float nn1  = sqrtf(ns1) + 1e-8f;
            float inv0 = __fdividef(1.f, nn0);
            float inv1 = __fdividef(1.f, nn1);
            float fid0 = s_es[q]     * sqrtf(fmaf(dr0, dr0, di0 * di0)) * inv0;
            float fid1 = s_es[q + 1] * sqrtf(fmaf(dr1, dr1, di1 * di1)) * inv1;
            bool flip0 = px0 != (fid0 < 0.9f);        // warp-uniform
            bool flip1 = px1 != (fid1 < 0.9f);

            float mA0 = fabsf(gsA0), mB0 = fabsf(gsB0);
            float mA1 = fabsf(gsA1), mB1 = fabsf(gsB1);
            float oA0, oB0, oA1, oB1;
            if (flip0) {
                oA0 = __shfl_xor_sync(0xffffffffu, mB0, 31);
                oB0 = __shfl_xor_sync(0xffffffffu, mA0, 31);
            } else { oA0 = mA0; oB0 = mB0; }
            if (flip1) {
                oA1 = __shfl_xor_sync(0xffffffffu, mB1, 31);
                oB1 = __shfl_xor_sync(0xffffffffu, mA1, 31);
            } else { oA1 = mA1; oB1 = mB1; }

            orow2[q * 32 + lane]        = make_float2(oA0 * inv0, oB0 * inv0);
            orow2[(q + 1) * 32 + lane]  = make_float2(oA1 * inv1, oB1 * inv1);
        }
    }
}

extern "C" void kernel_launch(void* const* d_in, const int* in_sizes, int n_in,
                              void* d_out, int out_size) {
    const float* x   = (const float*)d_in[0];
    const float* rx  = (const float*)d_in[1];
    const float* ry  = (const float*)d_in[2];
    const float* rz  = (const float*)d_in[3];
    const float* ecc = (const float*)d_in[4];
    const float* syn = (const float*)d_in[5];
    float* out = (float*)d_out;

    qsetup<<<1, 256>>>(rx, ry, rz, ecc, syn);
    qmain<<<148 * 6, 32 * QW>>>(x, out);
}